// round 6
// baseline (speedup 1.0000x reference)
#include <cuda_runtime.h>
#include <math.h>

#define S_LEN 2048
#define BATCH 64
#define INSZ  512
#define HID   512
#define BH    (BATCH * HID)          // 32768
#define GATES 1024                   // compact z|n gates
#define M_TOT (S_LEN * BATCH)        // 131072

#define GCTA  128                    // persistent CTAs for recurrence
#define JPER  4                      // hidden units per CTA
#define KG    128                    // k-groups of 4 (HID/4)

// 512 MB scratch for x-projection (z|n gates, bias folded in)
__device__ float g_xp[(size_t)M_TOT * GATES];
// Transposed/packed h history: slot s holds h_{s-1} as [kgroup][b][4]
// (element (k,b) at (k>>2)*256 + b*4 + (k&3)). Slot 0 is h_0 = 0: it is
// zero-initialized at module load and NEVER written (epilogue writes slots
// 1..S_LEN), so it stays zero across graph replays.
__device__ float g_hT[(size_t)(S_LEN + 1) * BH];
__device__ unsigned g_count;   // zero-init; reset by tail handshake each run
__device__ unsigned g_sense;
__device__ unsigned g_done;

// ---------------- packed fp32x2 helpers (B300 FFMA2 pipe) ----------------
__device__ __forceinline__ void fma2(unsigned long long& d,
                                     unsigned long long a,
                                     unsigned long long b) {
    asm("fma.rn.f32x2 %0, %1, %2, %0;" : "+l"(d) : "l"(a), "l"(b));
}
__device__ __forceinline__ unsigned long long dup2(float x) {
    unsigned long long r;
    asm("mov.b64 %0, {%1, %1};" : "=l"(r) : "f"(x));
    return r;
}
__device__ __forceinline__ float2 unpack2(unsigned long long v) {
    float2 f;
    asm("mov.b64 {%0, %1}, %2;" : "=f"(f.x), "=f"(f.y) : "l"(v));
    return f;
}

// ---------------------------------------------------------------------------
// Phase 1: C[m][n] = sum_k x[m][k] * Wih[HID + n][k] + bias[HID + n]
// 128x128x8 tiled SGEMM, 256 threads, 8x8 per-thread micro-tile, FFMA2.
// ---------------------------------------------------------------------------
__global__ __launch_bounds__(256, 2) void xproj_kernel(
    const float* __restrict__ A,     // x  [M_TOT, INSZ]
    const float* __restrict__ Wih,   // [3H, INSZ]
    const float* __restrict__ bias)  // [3H]
{
    __shared__ float As[8][128];
    __shared__ float Bs[8][128];

    const int bx  = blockIdx.x;      // n tile (8)
    const int by  = blockIdx.y;      // m tile (1024)
    const int tid = threadIdx.x;

    const int lrow = tid >> 1;           // 0..127
    const int lcol = (tid & 1) * 4;      // 0 or 4

    const float* Aptr = A   + (size_t)(by * 128 + lrow) * INSZ + lcol;
    const float* Wptr = Wih + (size_t)(HID + bx * 128 + lrow) * INSZ + lcol;

    const int ty = tid >> 4;   // 0..15 (m)
    const int tx = tid & 15;   // 0..15 (n)

    unsigned long long acc[8][4];
#pragma unroll
    for (int i = 0; i < 8; i++)
#pragma unroll
        for (int j = 0; j < 4; j++) acc[i][j] = 0ULL;

    for (int k0 = 0; k0 < INSZ; k0 += 8) {
        float4 av = *(const float4*)(Aptr + k0);
        float4 bv = *(const float4*)(Wptr + k0);
        As[lcol + 0][lrow] = av.x;
        As[lcol + 1][lrow] = av.y;
        As[lcol + 2][lrow] = av.z;
        As[lcol + 3][lrow] = av.w;
        Bs[lcol + 0][lrow] = bv.x;
        Bs[lcol + 1][lrow] = bv.y;
        Bs[lcol + 2][lrow] = bv.z;
        Bs[lcol + 3][lrow] = bv.w;
        __syncthreads();

#pragma unroll
        for (int k = 0; k < 8; k++) {
            float4 a0 = *(const float4*)&As[k][ty * 8];
            float4 a1 = *(const float4*)&As[k][ty * 8 + 4];
            ulonglong2 b0 = *(const ulonglong2*)&Bs[k][tx * 8];
            ulonglong2 b1 = *(const ulonglong2*)&Bs[k][tx * 8 + 4];
            float ar[8] = {a0.x, a0.y, a0.z, a0.w, a1.x, a1.y, a1.z, a1.w};
#pragma unroll
            for (int i = 0; i < 8; i++) {
                unsigned long long ad = dup2(ar[i]);
                fma2(acc[i][0], ad, b0.x);
                fma2(acc[i][1], ad, b0.y);
                fma2(acc[i][2], ad, b1.x);
                fma2(acc[i][3], ad, b1.y);
            }
        }
        __syncthreads();
    }

    const int n0 = bx * 128 + tx * 8;
    float bv[8];
#pragma unroll
    for (int j = 0; j < 8; j++) bv[j] = bias[HID + n0 + j];

    float* Cpt = g_xp + (size_t)(by * 128 + ty * 8) * GATES + n0;
#pragma unroll
    for (int i = 0; i < 8; i++) {
        float2 p0 = unpack2(acc[i][0]);
        float2 p1 = unpack2(acc[i][1]);
        float2 p2 = unpack2(acc[i][2]);
        float2 p3 = unpack2(acc[i][3]);
        float4 o0, o1;
        o0.x = p0.x + bv[0]; o0.y = p0.y + bv[1];
        o0.z = p1.x + bv[2]; o0.w = p1.y + bv[3];
        o1.x = p2.x + bv[4]; o1.y = p2.y + bv[5];
        o1.z = p3.x + bv[6]; o1.w = p3.y + bv[7];
        *(float4*)(Cpt + (size_t)i * GATES)     = o0;
        *(float4*)(Cpt + (size_t)i * GATES + 4) = o1;
    }
}

// ---------------------------------------------------------------------------
// Phase 2: persistent recurrence. 128 CTAs x 256 threads (one wave).
// CTA c owns hidden units j in [4c, 4c+4) (8 gate rows z|n cached in smem).
// Thread (lane, warp): b in {lane, lane+32}; warp -> (kq = warp>>1, rh = warp&1)
// handling rows {2rh, 2rh+1, 4+2rh, 5+2rh} over k-quarter kq.
// h read from packed g_hT slot t with coalesced LDG.128, 8 loads in flight.
// smem reduce over kq; 64 threads apply gates (h_old in regs), write h_t to
// out + one coalesced STG.128 into g_hT slot t+1. Grid barrier per step.
// ---------------------------------------------------------------------------
__global__ __launch_bounds__(256) void gru_kernel(
    const float* __restrict__ Whh,   // [3H, HID]
    float* __restrict__ out)         // [S*BH + BH]
{
    __shared__ float w_s[8 * HID];           // z rows then n rows, [8][512]
    __shared__ float red_s[4 * 8 * 64];      // [kq][row][b]

    const int tid   = threadIdx.x;
    const int lane  = tid & 31;
    const int warp  = tid >> 5;
    const int kq    = warp >> 1;             // 0..3
    const int rh    = warp & 1;              // 0..1
    const int jbase = blockIdx.x * JPER;

    // Load the 8 weight rows this CTA needs (once for the whole sequence).
    for (int i = tid; i < 8 * HID; i += 256) {
        int s = i >> 9, k = i & 511;
        int row = (s < 4) ? (HID + jbase + s) : (2 * HID + jbase + s - 4);
        w_s[i] = Whh[(size_t)row * HID + k];
    }
    __syncthreads();

    // Rows handled by this thread: z pair then n pair.
    const int R0 = 2 * rh, R1 = 2 * rh + 1, R2 = 4 + 2 * rh, R3 = 5 + 2 * rh;
    const float* w0 = w_s + R0 * HID + kq * 128;
    const float* w1 = w_s + R1 * HID + kq * 128;
    const float* w2p = w_s + R2 * HID + kq * 128;
    const float* w3p = w_s + R3 * HID + kq * 128;

    float hold[4] = {0.f, 0.f, 0.f, 0.f};    // h_{t-1}(b=tid, jbase..+4), tid<64

    for (int t = 0; t < S_LEN; t++) {
        // Prefetch xp for this step (independent of h; consumed after reduce).
        float4 xpz, xpn;
        if (tid < 64) {
            const float* xprow = g_xp + ((size_t)t * BATCH + tid) * GATES;
            xpz = *(const float4*)(xprow + jbase);
            xpn = *(const float4*)(xprow + HID + jbase);
        }

        // h slot t, this thread's k-quarter, two b values (lane, lane+32).
        const float* hs = g_hT + (size_t)t * BH + (size_t)(kq * 32) * 256 + lane * 4;

        unsigned long long acc[4][4];        // [row][ {b0e,b0o,b1e,b1o} ]
#pragma unroll
        for (int r = 0; r < 4; r++)
#pragma unroll
            for (int c = 0; c < 4; c++) acc[r][c] = 0ULL;

#pragma unroll
        for (int ch = 0; ch < 8; ch++) {     // 8 chunks x 4 k-groups
            ulonglong2 hA[4], hB[4];
#pragma unroll
            for (int g = 0; g < 4; g++) {
                const float* hp = hs + (size_t)(ch * 4 + g) * 256;
                hA[g] = *(const ulonglong2*)(hp);            // b = lane
                hB[g] = *(const ulonglong2*)(hp + 128);      // b = lane+32
            }
#pragma unroll
            for (int g = 0; g < 4; g++) {
                const int k0 = (ch * 4 + g) * 4;
                ulonglong2 wv0 = *(const ulonglong2*)(w0 + k0);
                ulonglong2 wv1 = *(const ulonglong2*)(w1 + k0);
                ulonglong2 wv2 = *(const ulonglong2*)(w2p + k0);
                ulonglong2 wv3 = *(const ulonglong2*)(w3p + k0);
                fma2(acc[0][0], hA[g].x, wv0.x); fma2(acc[0][1], hA[g].y, wv0.y);
                fma2(acc[0][2], hB[g].x, wv0.x); fma2(acc[0][3], hB[g].y, wv0.y);
                fma2(acc[1][0], hA[g].x, wv1.x); fma2(acc[1][1], hA[g].y, wv1.y);
                fma2(acc[1][2], hB[g].x, wv1.x); fma2(acc[1][3], hB[g].y, wv1.y);
                fma2(acc[2][0], hA[g].x, wv2.x); fma2(acc[2][1], hA[g].y, wv2.y);
                fma2(acc[2][2], hB[g].x, wv2.x); fma2(acc[2][3], hB[g].y, wv2.y);
                fma2(acc[3][0], hA[g].x, wv3.x); fma2(acc[3][1], hA[g].y, wv3.y);
                fma2(acc[3][2], hB[g].x, wv3.x); fma2(acc[3][3], hB[g].y, wv3.y);
            }
        }

        // Collapse packed accumulators; write partials [kq][row][b].
        const int rows[4] = {R0, R1, R2, R3};
#pragma unroll
        for (int r = 0; r < 4; r++) {
            float2 e0 = unpack2(acc[r][0]);
            float2 o0 = unpack2(acc[r][1]);
            float2 e1 = unpack2(acc[r][2]);
            float2 o1 = unpack2(acc[r][3]);
            red_s[kq * 512 + rows[r] * 64 + lane]      = (e0.x + e0.y) + (o0.x + o0.y);
            red_s[kq * 512 + rows[r] * 64 + lane + 32] = (e1.x + e1.y) + (o1.x + o1.y);
        }
        __syncthreads();

        if (tid < 64) {
            const int b = tid;
            float sum[8];
#pragma unroll
            for (int r = 0; r < 8; r++) {
                float p0 = red_s[          r * 64 + b];
                float p1 = red_s[1 * 512 + r * 64 + b];
                float p2 = red_s[2 * 512 + r * 64 + b];
                float p3 = red_s[3 * 512 + r * 64 + b];
                sum[r] = (p0 + p1) + (p2 + p3);
            }
            const float* xz = (const float*)&xpz;
            const float* xn = (const float*)&xpn;
            float hv[4];
#pragma unroll
            for (int jj = 0; jj < 4; jj++) {
                float gz = sum[jj] + xz[jj];
                float gn = sum[4 + jj] + xn[jj];
                float z  = 1.f / (1.f + __expf(-gz));
                float e  = __expf(-2.f * fabsf(gn));          // in (0,1]
                float tt = (1.f - e) / (1.f + e);
                float n  = copysignf(tt, gn);
                hv[jj] = (1.f - z) * n + z * hold[jj];
                hold[jj] = hv[jj];
            }
            float4 hq = {hv[0], hv[1], hv[2], hv[3]};
            *(float4*)(out + (size_t)t * BH + b * HID + jbase) = hq;
            // Packed transposed h for next step: one coalesced STG.128.
            *(float4*)(g_hT + (size_t)(t + 1) * BH + (size_t)(jbase >> 2) * 256 + b * 4) = hq;
            if (t == S_LEN - 1)
                *(float4*)(out + (size_t)S_LEN * BH + b * HID + jbase) = hq;
        }

        __syncthreads();
        if (t < S_LEN - 1) {
            // ---- grid-wide barrier (monotonic count) ----
            if (tid == 0) {
                __threadfence();
                unsigned target = (unsigned)(t + 1) * GCTA;
                unsigned old = atomicAdd(&g_count, 1u);
                if (old == target - 1u) {
                    __threadfence();
                    *((volatile unsigned*)&g_sense) = (unsigned)(t + 1);
                } else {
                    while (*((volatile unsigned*)&g_sense) < (unsigned)(t + 1)) {}
                }
                __threadfence();
            }
            __syncthreads();
        }
    }

    // Tail handshake: last CTA to arrive resets barrier state for the next
    // graph replay (all other CTAs have already passed every barrier).
    if (tid == 0) {
        __threadfence();
        unsigned old = atomicAdd(&g_done, 1u);
        if (old == GCTA - 1u) {
            g_count = 0u;
            g_sense = 0u;
            g_done  = 0u;
            __threadfence();
        }
    }
}

extern "C" void kernel_launch(void* const* d_in, const int* in_sizes, int n_in,
                              void* d_out, int out_size) {
    const float* x    = (const float*)d_in[0];
    const float* wih  = (const float*)d_in[1];
    const float* whh  = (const float*)d_in[2];
    const float* bias = (const float*)d_in[3];
    float* out = (float*)d_out;

    dim3 grid1(GATES / 128, M_TOT / 128);
    xproj_kernel<<<grid1, 256>>>(x, wih, bias);

    gru_kernel<<<GCTA, 256>>>(whh, out);
}

// round 9
// speedup vs baseline: 1.2411x; 1.2411x over previous
#include <cuda_runtime.h>
#include <math.h>

#define S_LEN 2048
#define BATCH 64
#define INSZ  512
#define HID   512
#define BH    (BATCH * HID)          // 32768
#define GATES 1024                   // compact z|n gates
#define M_TOT (S_LEN * BATCH)        // 131072

#define NGROUP 8                     // independent batch groups
#define GSIZE  16                    // CTAs per group (j-slices)
#define BPG    8                     // batch rows per group
#define JPC    32                    // hidden units per CTA
#define WSTR   1032                  // per-j weight stride in floats (2*516)
#define HSTR   516                   // per-b h stride in floats

// 512 MB scratch for x-projection (z|n gates, bias folded in)
__device__ float g_xp[(size_t)M_TOT * GATES];
// Per-group barrier state (zero-init; reset by per-group tail handshake)
__device__ unsigned g_cnt[NGROUP];
__device__ unsigned g_sense[NGROUP];
__device__ unsigned g_done[NGROUP];

// ---------------- packed fp32x2 helpers (B300 FFMA2 pipe) ----------------
__device__ __forceinline__ void fma2(unsigned long long& d,
                                     unsigned long long a,
                                     unsigned long long b) {
    asm("fma.rn.f32x2 %0, %1, %2, %0;" : "+l"(d) : "l"(a), "l"(b));
}
__device__ __forceinline__ unsigned long long dup2(float x) {
    unsigned long long r;
    asm("mov.b64 %0, {%1, %1};" : "=l"(r) : "f"(x));
    return r;
}
__device__ __forceinline__ float2 unpack2(unsigned long long v) {
    float2 f;
    asm("mov.b64 {%0, %1}, %2;" : "=f"(f.x), "=f"(f.y) : "l"(v));
    return f;
}
// ---------------- acquire/release sync (no L1-flushing fences) -----------
__device__ __forceinline__ unsigned atom_add_acqrel(unsigned* p, unsigned v) {
    unsigned r;
    asm volatile("atom.acq_rel.gpu.add.u32 %0, [%1], %2;"
                 : "=r"(r) : "l"(p), "r"(v) : "memory");
    return r;
}
__device__ __forceinline__ unsigned ld_acq(unsigned* p) {
    unsigned r;
    asm volatile("ld.acquire.gpu.u32 %0, [%1];" : "=r"(r) : "l"(p) : "memory");
    return r;
}
__device__ __forceinline__ void st_rel(unsigned* p, unsigned v) {
    asm volatile("st.release.gpu.u32 [%0], %1;" :: "l"(p), "r"(v) : "memory");
}

// ---------------------------------------------------------------------------
// Phase 1: C[m][n] = sum_k x[m][k] * Wih[HID + n][k] + bias[HID + n]
// 128x128x8 tiled SGEMM, 256 threads, 8x8 per-thread micro-tile, FFMA2.
// ---------------------------------------------------------------------------
__global__ __launch_bounds__(256, 2) void xproj_kernel(
    const float* __restrict__ A,     // x  [M_TOT, INSZ]
    const float* __restrict__ Wih,   // [3H, INSZ]
    const float* __restrict__ bias)  // [3H]
{
    __shared__ float As[8][128];
    __shared__ float Bs[8][128];

    const int bx  = blockIdx.x;      // n tile (8)
    const int by  = blockIdx.y;      // m tile (1024)
    const int tid = threadIdx.x;

    const int lrow = tid >> 1;           // 0..127
    const int lcol = (tid & 1) * 4;      // 0 or 4

    const float* Aptr = A   + (size_t)(by * 128 + lrow) * INSZ + lcol;
    const float* Wptr = Wih + (size_t)(HID + bx * 128 + lrow) * INSZ + lcol;

    const int ty = tid >> 4;   // 0..15 (m)
    const int tx = tid & 15;   // 0..15 (n)

    unsigned long long acc[8][4];
#pragma unroll
    for (int i = 0; i < 8; i++)
#pragma unroll
        for (int j = 0; j < 4; j++) acc[i][j] = 0ULL;

    for (int k0 = 0; k0 < INSZ; k0 += 8) {
        float4 av = *(const float4*)(Aptr + k0);
        float4 bv = *(const float4*)(Wptr + k0);
        As[lcol + 0][lrow] = av.x;
        As[lcol + 1][lrow] = av.y;
        As[lcol + 2][lrow] = av.z;
        As[lcol + 3][lrow] = av.w;
        Bs[lcol + 0][lrow] = bv.x;
        Bs[lcol + 1][lrow] = bv.y;
        Bs[lcol + 2][lrow] = bv.z;
        Bs[lcol + 3][lrow] = bv.w;
        __syncthreads();

#pragma unroll
        for (int k = 0; k < 8; k++) {
            float4 a0 = *(const float4*)&As[k][ty * 8];
            float4 a1 = *(const float4*)&As[k][ty * 8 + 4];
            ulonglong2 b0 = *(const ulonglong2*)&Bs[k][tx * 8];
            ulonglong2 b1 = *(const ulonglong2*)&Bs[k][tx * 8 + 4];
            float ar[8] = {a0.x, a0.y, a0.z, a0.w, a1.x, a1.y, a1.z, a1.w};
#pragma unroll
            for (int i = 0; i < 8; i++) {
                unsigned long long ad = dup2(ar[i]);
                fma2(acc[i][0], ad, b0.x);
                fma2(acc[i][1], ad, b0.y);
                fma2(acc[i][2], ad, b1.x);
                fma2(acc[i][3], ad, b1.y);
            }
        }
        __syncthreads();
    }

    const int n0 = bx * 128 + tx * 8;
    float bv[8];
#pragma unroll
    for (int j = 0; j < 8; j++) bv[j] = bias[HID + n0 + j];

    float* Cpt = g_xp + (size_t)(by * 128 + ty * 8) * GATES + n0;
#pragma unroll
    for (int i = 0; i < 8; i++) {
        float2 p0 = unpack2(acc[i][0]);
        float2 p1 = unpack2(acc[i][1]);
        float2 p2 = unpack2(acc[i][2]);
        float2 p3 = unpack2(acc[i][3]);
        float4 o0, o1;
        o0.x = p0.x + bv[0]; o0.y = p0.y + bv[1];
        o0.z = p1.x + bv[2]; o0.w = p1.y + bv[3];
        o1.x = p2.x + bv[4]; o1.y = p2.y + bv[5];
        o1.z = p3.x + bv[6]; o1.w = p3.y + bv[7];
        *(float4*)(Cpt + (size_t)i * GATES)     = o0;
        *(float4*)(Cpt + (size_t)i * GATES + 4) = o1;
    }
}

// ---------------------------------------------------------------------------
// Phase 2: batch-grouped recurrence. 128 CTAs x 256 threads = 8 groups x 16.
// Group g owns batch rows [8g, 8g+8); CTA slice i owns 32 hidden units whose
// 64 gate rows (z|n) live in smem for the whole sequence. Thread (b,j) owns
// the FULL z and n dot products for its (b,j) and applies the gates itself
// (h_old in a register). h exchanged through out[t-1] (fresh per step).
// Only a 16-CTA per-group acq_rel barrier per step — no gpu-scope fences.
// ---------------------------------------------------------------------------
extern __shared__ float smem[];

__global__ __launch_bounds__(256) void gru_kernel(
    const float* __restrict__ Whh,   // [3H, HID]
    float* __restrict__ out)         // [S*BH + BH]
{
    float* w_s = smem;                   // [JPC][2][516] padded (z,n per j)
    float* h_s = smem + JPC * WSTR;      // [BPG][516] padded

    const int tid   = threadIdx.x;
    const int lane  = tid & 31;
    const int warp  = tid >> 5;          // 0..7
    const int grp   = blockIdx.x >> 4;   // 0..7
    const int slice = blockIdx.x & 15;   // 0..15
    const int jbase = slice * JPC;
    const int b_l   = lane >> 2;         // 0..7  batch row within group
    const int j_l   = warp * 4 + (lane & 3);   // 0..31 hidden unit within CTA
    const int b_g   = grp * BPG + b_l;
    const int j_g   = jbase + j_l;

    // Load the 64 gate rows this CTA needs (once for the whole sequence).
    for (int i = tid; i < 64 * HID; i += 256) {
        int r = i >> 9;                  // 0..63
        int k = i & 511;
        int jl = r & 31;
        int row = ((r < 32) ? HID : 2 * HID) + jbase + jl;
        w_s[jl * WSTR + ((r < 32) ? 0 : HSTR) + k] = Whh[(size_t)row * HID + k];
    }
    __syncthreads();

    const float* wz = w_s + j_l * WSTR;
    const float* wn = wz + HSTR;
    const float* hb = h_s + b_l * HSTR;
    unsigned* cntp   = &g_cnt[grp];
    unsigned* sensep = &g_sense[grp];

    float hold = 0.f;                    // h_{t-1}(b_g, j_g)

    for (int t = 0; t < S_LEN; t++) {
        // xp prefetch (independent of h)
        const float* xprow = g_xp + ((size_t)t * BATCH + b_g) * GATES;
        float xpz = xprow[j_g];
        float xpn = xprow[HID + j_g];

        float sz = 0.f, sn = 0.f;
        if (t > 0) {
            // Stage this group's 8 h rows (16 KB) from out[t-1].
            const float* hsrc = out + (size_t)(t - 1) * BH + (size_t)grp * BPG * HID;
            for (int idx = tid; idx < 1024; idx += 256) {
                int bb = idx >> 7, k4 = (idx & 127) << 2;
                float4 v = *(const float4*)(hsrc + bb * HID + k4);
                *(float4*)(h_s + bb * HSTR + k4) = v;
            }
            __syncthreads();

            // Full-coverage dot: each ulonglong2 = 4 floats; four loads per
            // 16-float chunk (kc, +4, +8, +12). (R7/R8 bug: stride-16 loop
            // loaded only kc and kc+8 -> half the k terms silently skipped.)
            unsigned long long az0 = 0, az1 = 0, az2 = 0, az3 = 0;
            unsigned long long an0 = 0, an1 = 0, an2 = 0, an3 = 0;
#pragma unroll 4
            for (int kc = 0; kc < HID; kc += 16) {
                ulonglong2 h0 = *(const ulonglong2*)(hb + kc);
                ulonglong2 h1 = *(const ulonglong2*)(hb + kc + 4);
                ulonglong2 h2 = *(const ulonglong2*)(hb + kc + 8);
                ulonglong2 h3 = *(const ulonglong2*)(hb + kc + 12);
                ulonglong2 z0 = *(const ulonglong2*)(wz + kc);
                ulonglong2 z1 = *(const ulonglong2*)(wz + kc + 4);
                ulonglong2 z2 = *(const ulonglong2*)(wz + kc + 8);
                ulonglong2 z3 = *(const ulonglong2*)(wz + kc + 12);
                ulonglong2 n0 = *(const ulonglong2*)(wn + kc);
                ulonglong2 n1 = *(const ulonglong2*)(wn + kc + 4);
                ulonglong2 n2 = *(const ulonglong2*)(wn + kc + 8);
                ulonglong2 n3 = *(const ulonglong2*)(wn + kc + 12);
                fma2(az0, h0.x, z0.x); fma2(az1, h0.y, z0.y);
                fma2(az2, h1.x, z1.x); fma2(az3, h1.y, z1.y);
                fma2(an0, h0.x, n0.x); fma2(an1, h0.y, n0.y);
                fma2(an2, h1.x, n1.x); fma2(an3, h1.y, n1.y);
                fma2(az0, h2.x, z2.x); fma2(az1, h2.y, z2.y);
                fma2(az2, h3.x, z3.x); fma2(az3, h3.y, z3.y);
                fma2(an0, h2.x, n2.x); fma2(an1, h2.y, n2.y);
                fma2(an2, h3.x, n3.x); fma2(an3, h3.y, n3.y);
            }
            float2 e0 = unpack2(az0), e1 = unpack2(az1);
            float2 e2 = unpack2(az2), e3 = unpack2(az3);
            sz = ((e0.x + e0.y) + (e1.x + e1.y)) + ((e2.x + e2.y) + (e3.x + e3.y));
            float2 f0 = unpack2(an0), f1 = unpack2(an1);
            float2 f2 = unpack2(an2), f3 = unpack2(an3);
            sn = ((f0.x + f0.y) + (f1.x + f1.y)) + ((f2.x + f2.y) + (f3.x + f3.y));
        }

        // Gates + state update (every thread owns its own (b,j)).
        float gz = sz + xpz;
        float gn = sn + xpn;
        float z  = 1.f / (1.f + __expf(-gz));
        float e  = __expf(-2.f * fabsf(gn));        // in (0,1]
        float tt = (1.f - e) / (1.f + e);
        float n  = copysignf(tt, gn);
        float hn = (1.f - z) * n + z * hold;
        hold = hn;

        out[(size_t)t * BH + (size_t)b_g * HID + j_g] = hn;
        if (t == S_LEN - 1)
            out[(size_t)S_LEN * BH + (size_t)b_g * HID + j_g] = hn;

        __syncthreads();                 // all CTA stores issued
        if (t < S_LEN - 1) {
            // ---- per-group 16-CTA barrier (acq_rel arrivals, monotonic) ----
            if (tid == 0) {
                unsigned target = (unsigned)(t + 1) * GSIZE;
                unsigned old = atom_add_acqrel(cntp, 1u);
                if (old == target - 1u) {
                    st_rel(sensep, (unsigned)(t + 1));
                } else {
                    while (ld_acq(sensep) < (unsigned)(t + 1)) {}
                }
            }
            __syncthreads();
        }
    }

    // Per-group tail handshake: last CTA resets barrier state for next replay.
    if (tid == 0) {
        unsigned old = atom_add_acqrel(&g_done[grp], 1u);
        if (old == GSIZE - 1u) {
            st_rel(&g_cnt[grp], 0u);
            st_rel(&g_sense[grp], 0u);
            st_rel(&g_done[grp], 0u);
        }
    }
}

extern "C" void kernel_launch(void* const* d_in, const int* in_sizes, int n_in,
                              void* d_out, int out_size) {
    const float* x    = (const float*)d_in[0];
    const float* wih  = (const float*)d_in[1];
    const float* whh  = (const float*)d_in[2];
    const float* bias = (const float*)d_in[3];
    float* out = (float*)d_out;

    static int configured = 0;
    if (!configured) {
        cudaFuncSetAttribute(gru_kernel,
                             cudaFuncAttributeMaxDynamicSharedMemorySize,
                             (JPC * WSTR + BPG * HSTR) * sizeof(float));
        configured = 1;
    }

    dim3 grid1(GATES / 128, M_TOT / 128);
    xproj_kernel<<<grid1, 256>>>(x, wih, bias);

    size_t smem_bytes = (JPC * WSTR + BPG * HSTR) * sizeof(float);
    gru_kernel<<<NGROUP * GSIZE, 256, smem_bytes>>>(whh, out);
}

// round 10
// speedup vs baseline: 1.2970x; 1.0450x over previous
#include <cuda_runtime.h>
#include <math.h>

#define S_LEN 2048
#define BATCH 64
#define INSZ  512
#define HID   512
#define BH    (BATCH * HID)          // 32768
#define GATES 1024                   // compact z|n gates
#define M_TOT (S_LEN * BATCH)        // 131072

#define NGROUP 8                     // independent batch groups
#define GSIZE  16                    // CTAs per group (j-slices)
#define BPG    8                     // batch rows per group
#define JPC    32                    // hidden units per CTA
#define WSTR   1032                  // per-j weight stride in floats (2*516)
#define HSTR   516                   // per-b h stride in floats
#define GTHR   1024                  // threads per gru CTA (32 warps)

// 512 MB scratch for x-projection (z|n gates, bias folded in)
__device__ float g_xp[(size_t)M_TOT * GATES];
// Per-group barrier state (zero-init; reset by per-group tail handshake)
__device__ unsigned g_cnt[NGROUP];
__device__ unsigned g_sense[NGROUP];
__device__ unsigned g_done[NGROUP];

// ---------------- packed fp32x2 helpers (B300 FFMA2 pipe) ----------------
__device__ __forceinline__ void fma2(unsigned long long& d,
                                     unsigned long long a,
                                     unsigned long long b) {
    asm("fma.rn.f32x2 %0, %1, %2, %0;" : "+l"(d) : "l"(a), "l"(b));
}
__device__ __forceinline__ unsigned long long dup2(float x) {
    unsigned long long r;
    asm("mov.b64 %0, {%1, %1};" : "=l"(r) : "f"(x));
    return r;
}
__device__ __forceinline__ float2 unpack2(unsigned long long v) {
    float2 f;
    asm("mov.b64 {%0, %1}, %2;" : "=f"(f.x), "=f"(f.y) : "l"(v));
    return f;
}
// ---------------- acquire/release sync (no L1-flushing fences) -----------
__device__ __forceinline__ unsigned atom_add_acqrel(unsigned* p, unsigned v) {
    unsigned r;
    asm volatile("atom.acq_rel.gpu.add.u32 %0, [%1], %2;"
                 : "=r"(r) : "l"(p), "r"(v) : "memory");
    return r;
}
__device__ __forceinline__ unsigned ld_acq(unsigned* p) {
    unsigned r;
    asm volatile("ld.acquire.gpu.u32 %0, [%1];" : "=r"(r) : "l"(p) : "memory");
    return r;
}
__device__ __forceinline__ void st_rel(unsigned* p, unsigned v) {
    asm volatile("st.release.gpu.u32 [%0], %1;" :: "l"(p), "r"(v) : "memory");
}

// ---------------------------------------------------------------------------
// Phase 1: C[m][n] = sum_k x[m][k] * Wih[HID + n][k] + bias[HID + n]
// 128x128x8 tiled SGEMM, 256 threads, 8x8 per-thread micro-tile, FFMA2.
// ---------------------------------------------------------------------------
__global__ __launch_bounds__(256, 2) void xproj_kernel(
    const float* __restrict__ A,     // x  [M_TOT, INSZ]
    const float* __restrict__ Wih,   // [3H, INSZ]
    const float* __restrict__ bias)  // [3H]
{
    __shared__ float As[8][128];
    __shared__ float Bs[8][128];

    const int bx  = blockIdx.x;      // n tile (8)
    const int by  = blockIdx.y;      // m tile (1024)
    const int tid = threadIdx.x;

    const int lrow = tid >> 1;           // 0..127
    const int lcol = (tid & 1) * 4;      // 0 or 4

    const float* Aptr = A   + (size_t)(by * 128 + lrow) * INSZ + lcol;
    const float* Wptr = Wih + (size_t)(HID + bx * 128 + lrow) * INSZ + lcol;

    const int ty = tid >> 4;   // 0..15 (m)
    const int tx = tid & 15;   // 0..15 (n)

    unsigned long long acc[8][4];
#pragma unroll
    for (int i = 0; i < 8; i++)
#pragma unroll
        for (int j = 0; j < 4; j++) acc[i][j] = 0ULL;

    for (int k0 = 0; k0 < INSZ; k0 += 8) {
        float4 av = *(const float4*)(Aptr + k0);
        float4 bv = *(const float4*)(Wptr + k0);
        As[lcol + 0][lrow] = av.x;
        As[lcol + 1][lrow] = av.y;
        As[lcol + 2][lrow] = av.z;
        As[lcol + 3][lrow] = av.w;
        Bs[lcol + 0][lrow] = bv.x;
        Bs[lcol + 1][lrow] = bv.y;
        Bs[lcol + 2][lrow] = bv.z;
        Bs[lcol + 3][lrow] = bv.w;
        __syncthreads();

#pragma unroll
        for (int k = 0; k < 8; k++) {
            float4 a0 = *(const float4*)&As[k][ty * 8];
            float4 a1 = *(const float4*)&As[k][ty * 8 + 4];
            ulonglong2 b0 = *(const ulonglong2*)&Bs[k][tx * 8];
            ulonglong2 b1 = *(const ulonglong2*)&Bs[k][tx * 8 + 4];
            float ar[8] = {a0.x, a0.y, a0.z, a0.w, a1.x, a1.y, a1.z, a1.w};
#pragma unroll
            for (int i = 0; i < 8; i++) {
                unsigned long long ad = dup2(ar[i]);
                fma2(acc[i][0], ad, b0.x);
                fma2(acc[i][1], ad, b0.y);
                fma2(acc[i][2], ad, b1.x);
                fma2(acc[i][3], ad, b1.y);
            }
        }
        __syncthreads();
    }

    const int n0 = bx * 128 + tx * 8;
    float bv[8];
#pragma unroll
    for (int j = 0; j < 8; j++) bv[j] = bias[HID + n0 + j];

    float* Cpt = g_xp + (size_t)(by * 128 + ty * 8) * GATES + n0;
#pragma unroll
    for (int i = 0; i < 8; i++) {
        float2 p0 = unpack2(acc[i][0]);
        float2 p1 = unpack2(acc[i][1]);
        float2 p2 = unpack2(acc[i][2]);
        float2 p3 = unpack2(acc[i][3]);
        float4 o0, o1;
        o0.x = p0.x + bv[0]; o0.y = p0.y + bv[1];
        o0.z = p1.x + bv[2]; o0.w = p1.y + bv[3];
        o1.x = p2.x + bv[4]; o1.y = p2.y + bv[5];
        o1.z = p3.x + bv[6]; o1.w = p3.y + bv[7];
        *(float4*)(Cpt + (size_t)i * GATES)     = o0;
        *(float4*)(Cpt + (size_t)i * GATES + 4) = o1;
    }
}

// ---------------------------------------------------------------------------
// Phase 2: batch-grouped recurrence. 128 CTAs x 1024 threads = 8 groups x 16.
// Group g owns batch rows [8g, 8g+8); CTA slice owns 32 hidden units (64 gate
// rows z|n smem-resident). k split 4 ways across warp octets: warp octet kq
// computes the k-quarter partial for all (b,j); partials reduced through a
// small conflict-free smem array; warps 0-7 apply gates (h_old in registers)
// and store h. 16-CTA per-group acq_rel barrier per step.
// 32 warps/SM (occ 50%) to hide LDS latency — R9 ran at 8 warps, issue 14.5%.
// ---------------------------------------------------------------------------
extern __shared__ float smem[];

__global__ __launch_bounds__(GTHR) void gru_kernel(
    const float* __restrict__ Whh,   // [3H, HID]
    float* __restrict__ out)         // [S*BH + BH]
{
    float* w_s   = smem;                       // [JPC][2][516] (z,n per j)
    float* h_s   = smem + JPC * WSTR;          // [BPG][516]
    float* red_z = h_s + BPG * HSTR;           // [3][256]
    float* red_n = red_z + 3 * 256;            // [3][256]

    const int tid   = threadIdx.x;
    const int lane  = tid & 31;
    const int warp  = tid >> 5;          // 0..31
    const int kq    = warp >> 3;         // 0..3  k-quarter
    const int w8    = warp & 7;          // 0..7  warp within octet
    const int grp   = blockIdx.x >> 4;   // 0..7
    const int slice = blockIdx.x & 15;   // 0..15
    const int jbase = slice * JPC;
    const int b_l   = lane >> 2;         // 0..7  batch row within group
    const int j_l   = w8 * 4 + (lane & 3);     // 0..31 hidden unit within CTA
    const int b_g   = grp * BPG + b_l;
    const int j_g   = jbase + j_l;
    const int ridx  = w8 * 32 + lane;    // 0..255 output index within CTA

    // Load the 64 gate rows this CTA needs (once for the whole sequence).
    for (int i = tid; i < 64 * HID; i += GTHR) {
        int r = i >> 9;                  // 0..63
        int k = i & 511;
        int jl = r & 31;
        int row = ((r < 32) ? HID : 2 * HID) + jbase + jl;
        w_s[jl * WSTR + ((r < 32) ? 0 : HSTR) + k] = Whh[(size_t)row * HID + k];
    }
    __syncthreads();

    const float* wz = w_s + j_l * WSTR + kq * 128;
    const float* wn = wz + HSTR;
    const float* hb = h_s + b_l * HSTR + kq * 128;
    unsigned* cntp   = &g_cnt[grp];
    unsigned* sensep = &g_sense[grp];

    float hold = 0.f;                    // h_{t-1}(b_g, j_g), warps 0-7 only

    for (int t = 0; t < S_LEN; t++) {
        // xp prefetch (independent of h; epilogue warps only)
        float xpz = 0.f, xpn = 0.f;
        if (warp < 8) {
            const float* xprow = g_xp + ((size_t)t * BATCH + b_g) * GATES;
            xpz = xprow[j_g];
            xpn = xprow[HID + j_g];
        }

        float sz = 0.f, sn = 0.f;
        if (t > 0) {
            // Stage this group's 8 h rows (16 KB): one float4 per thread.
            {
                const float* hsrc = out + (size_t)(t - 1) * BH + (size_t)grp * BPG * HID;
                int bb = tid >> 7, k4 = (tid & 127) << 2;
                float4 v = *(const float4*)(hsrc + bb * HID + k4);
                *(float4*)(h_s + bb * HSTR + k4) = v;
            }
            __syncthreads();

            // 128-long packed dot for this (b, j, kq).
            unsigned long long az0 = 0, az1 = 0, az2 = 0, az3 = 0;
            unsigned long long an0 = 0, an1 = 0, an2 = 0, an3 = 0;
#pragma unroll
            for (int kc = 0; kc < 128; kc += 16) {
                ulonglong2 h0 = *(const ulonglong2*)(hb + kc);
                ulonglong2 h1 = *(const ulonglong2*)(hb + kc + 4);
                ulonglong2 h2 = *(const ulonglong2*)(hb + kc + 8);
                ulonglong2 h3 = *(const ulonglong2*)(hb + kc + 12);
                ulonglong2 z0 = *(const ulonglong2*)(wz + kc);
                ulonglong2 z1 = *(const ulonglong2*)(wz + kc + 4);
                ulonglong2 z2 = *(const ulonglong2*)(wz + kc + 8);
                ulonglong2 z3 = *(const ulonglong2*)(wz + kc + 12);
                ulonglong2 n0 = *(const ulonglong2*)(wn + kc);
                ulonglong2 n1 = *(const ulonglong2*)(wn + kc + 4);
                ulonglong2 n2 = *(const ulonglong2*)(wn + kc + 8);
                ulonglong2 n3 = *(const ulonglong2*)(wn + kc + 12);
                fma2(az0, h0.x, z0.x); fma2(az1, h0.y, z0.y);
                fma2(az2, h1.x, z1.x); fma2(az3, h1.y, z1.y);
                fma2(an0, h0.x, n0.x); fma2(an1, h0.y, n0.y);
                fma2(an2, h1.x, n1.x); fma2(an3, h1.y, n1.y);
                fma2(az0, h2.x, z2.x); fma2(az1, h2.y, z2.y);
                fma2(az2, h3.x, z3.x); fma2(az3, h3.y, z3.y);
                fma2(an0, h2.x, n2.x); fma2(an1, h2.y, n2.y);
                fma2(an2, h3.x, n3.x); fma2(an3, h3.y, n3.y);
            }
            float2 e0 = unpack2(az0), e1 = unpack2(az1);
            float2 e2 = unpack2(az2), e3 = unpack2(az3);
            sz = ((e0.x + e0.y) + (e1.x + e1.y)) + ((e2.x + e2.y) + (e3.x + e3.y));
            float2 f0 = unpack2(an0), f1 = unpack2(an1);
            float2 f2 = unpack2(an2), f3 = unpack2(an3);
            sn = ((f0.x + f0.y) + (f1.x + f1.y)) + ((f2.x + f2.y) + (f3.x + f3.y));

            // Combine k-quarter partials (conflict-free: lane-consecutive).
            if (kq > 0) {
                red_z[(kq - 1) * 256 + ridx] = sz;
                red_n[(kq - 1) * 256 + ridx] = sn;
            }
            __syncthreads();
            if (kq == 0) {
                sz += (red_z[ridx] + red_z[256 + ridx]) + red_z[512 + ridx];
                sn += (red_n[ridx] + red_n[256 + ridx]) + red_n[512 + ridx];
            }
        }

        if (warp < 8) {
            // Gates + state update (this thread owns (b_g, j_g)).
            float gz = sz + xpz;
            float gn = sn + xpn;
            float z  = 1.f / (1.f + __expf(-gz));
            float e  = __expf(-2.f * fabsf(gn));        // in (0,1]
            float tt = (1.f - e) / (1.f + e);
            float n  = copysignf(tt, gn);
            float hn = (1.f - z) * n + z * hold;
            hold = hn;

            out[(size_t)t * BH + (size_t)b_g * HID + j_g] = hn;
            if (t == S_LEN - 1)
                out[(size_t)S_LEN * BH + (size_t)b_g * HID + j_g] = hn;
        }

        __syncthreads();                 // all CTA stores issued
        if (t < S_LEN - 1) {
            // ---- per-group 16-CTA barrier (acq_rel arrivals, monotonic) ----
            if (tid == 0) {
                unsigned target = (unsigned)(t + 1) * GSIZE;
                unsigned old = atom_add_acqrel(cntp, 1u);
                if (old == target - 1u) {
                    st_rel(sensep, (unsigned)(t + 1));
                } else {
                    while (ld_acq(sensep) < (unsigned)(t + 1)) {}
                }
            }
            __syncthreads();
        }
    }

    // Per-group tail handshake: last CTA resets barrier state for next replay.
    if (tid == 0) {
        unsigned old = atom_add_acqrel(&g_done[grp], 1u);
        if (old == GSIZE - 1u) {
            st_rel(&g_cnt[grp], 0u);
            st_rel(&g_sense[grp], 0u);
            st_rel(&g_done[grp], 0u);
        }
    }
}

extern "C" void kernel_launch(void* const* d_in, const int* in_sizes, int n_in,
                              void* d_out, int out_size) {
    const float* x    = (const float*)d_in[0];
    const float* wih  = (const float*)d_in[1];
    const float* whh  = (const float*)d_in[2];
    const float* bias = (const float*)d_in[3];
    float* out = (float*)d_out;

    const size_t smem_bytes =
        (JPC * WSTR + BPG * HSTR + 6 * 256) * sizeof(float);

    static int configured = 0;
    if (!configured) {
        cudaFuncSetAttribute(gru_kernel,
                             cudaFuncAttributeMaxDynamicSharedMemorySize,
                             (int)smem_bytes);
        configured = 1;
    }

    dim3 grid1(GATES / 128, M_TOT / 128);
    xproj_kernel<<<grid1, 256>>>(x, wih, bias);

    gru_kernel<<<NGROUP * GSIZE, GTHR, smem_bytes>>>(whh, out);
}